// round 13
// baseline (speedup 1.0000x reference)
#include <cuda_runtime.h>
#include <math.h>
#include <stdint.h>

#define S_LEN 4096
#define D_MODEL 1024
#define NUM_HEADS 16
#define D_K 64

// ---------------- scratch (no allocs allowed) ----------------
__device__ float g_Q[S_LEN * D_MODEL];
__device__ float g_K[S_LEN * D_MODEL];    // column-pair-permuted per head
__device__ float g_V[S_LEN * D_MODEL];    // row-pair-interleaved
__device__ float g_AT[S_LEN * D_MODEL];
__device__ float g_XH[S_LEN * D_MODEL];   // hi plane (k-permuted)
__device__ float g_XL[S_LEN * D_MODEL];   // lo plane (k-permuted)
__device__ float g_W1[D_MODEL * D_MODEL]; // tf32 Wq (k-permuted)
__device__ float g_W2[D_MODEL * D_MODEL]; // tf32 Wk
__device__ float g_W3[D_MODEL * D_MODEL]; // tf32 Wv / Wo

// ---------------- helpers ----------------
__device__ __forceinline__ float tf32r(float x) {
    uint32_t u;
    asm("cvt.rna.tf32.f32 %0, %1;" : "=r"(u) : "f"(x));
    return __uint_as_float(u);
}
__device__ __forceinline__ uint32_t fau(float x) { return __float_as_uint(x); }

__device__ __forceinline__ void mma_tf32(float* d, const uint32_t* a, uint32_t b0, uint32_t b1) {
    asm volatile(
        "mma.sync.aligned.m16n8k8.row.col.f32.tf32.tf32.f32 "
        "{%0,%1,%2,%3}, {%4,%5,%6,%7}, {%8,%9}, {%0,%1,%2,%3};"
        : "+f"(d[0]), "+f"(d[1]), "+f"(d[2]), "+f"(d[3])
        : "r"(a[0]), "r"(a[1]), "r"(a[2]), "r"(a[3]), "r"(b0), "r"(b1));
}

__device__ __forceinline__ void cp_async16(uint32_t smem_addr, const void* gptr) {
    asm volatile("cp.async.cg.shared.global [%0], [%1], 16;\n"
                 :: "r"(smem_addr), "l"(gptr));
}
__device__ __forceinline__ void cp_commit() {
    asm volatile("cp.async.commit_group;\n" ::: "memory");
}
template<int N>
__device__ __forceinline__ void cp_wait() {
    asm volatile("cp.async.wait_group %0;\n" :: "n"(N) : "memory");
}

// k-pair permutation: within each 8-group, col w -> (w%4)*2 + w/4 (pairs (k,k+4) adjacent)
__device__ __forceinline__ int kperm(int c) {
    int w = c & 7;
    return (c & ~7) + ((w & 3) * 2) + (w >> 2);
}

// ---------------- prepasses (write k-permuted planes) ----------------
__global__ void split_kernel(const float4* __restrict__ src, float* __restrict__ hi,
                             float* __restrict__ lo, int n4) {
    int i = blockIdx.x * blockDim.x + threadIdx.x;
    if (i >= n4) return;
    float4 v = src[i];
    int b = i * 4;
    int d = (b & ~7) | ((b & 4) ? 1 : 0);
    float h0 = tf32r(v.x), h1 = tf32r(v.y), h2 = tf32r(v.z), h3 = tf32r(v.w);
    hi[d] = h0; hi[d + 2] = h1; hi[d + 4] = h2; hi[d + 6] = h3;
    lo[d] = tf32r(v.x - h0); lo[d + 2] = tf32r(v.y - h1);
    lo[d + 4] = tf32r(v.z - h2); lo[d + 6] = tf32r(v.w - h3);
}

__global__ void round3_kernel(const float4* __restrict__ s1, const float4* __restrict__ s2,
                              const float4* __restrict__ s3, float* __restrict__ d1,
                              float* __restrict__ d2, float* __restrict__ d3, int n4) {
    int i = blockIdx.x * blockDim.x + threadIdx.x;
    if (i >= n4) return;
    int b = i * 4;
    int d = (b & ~7) | ((b & 4) ? 1 : 0);
    float4 v = s1[i];
    d1[d] = tf32r(v.x); d1[d + 2] = tf32r(v.y); d1[d + 4] = tf32r(v.z); d1[d + 6] = tf32r(v.w);
    v = s2[i];
    d2[d] = tf32r(v.x); d2[d + 2] = tf32r(v.y); d2[d + 4] = tf32r(v.z); d2[d + 6] = tf32r(v.w);
    v = s3[i];
    d3[d] = tf32r(v.x); d3[d + 2] = tf32r(v.y); d3[d + 4] = tf32r(v.z); d3[d + 6] = tf32r(v.w);
}

__global__ void round1_kernel(const float4* __restrict__ src, float* __restrict__ dst, int n4) {
    int i = blockIdx.x * blockDim.x + threadIdx.x;
    if (i >= n4) return;
    int b = i * 4;
    int d = (b & ~7) | ((b & 4) ? 1 : 0);
    float4 v = src[i];
    dst[d] = tf32r(v.x); dst[d + 2] = tf32r(v.y); dst[d + 4] = tf32r(v.z); dst[d + 6] = tf32r(v.w);
}

// ---------------- 2xTF32 pipelined GEMM, k-pair-packed operands ----------------
// OUT mode: 0 = plain fp32, 1 = K layout (tf32 + col-pair permuted), 2 = V layout
// (tf32 + row-pair interleaved)
#define GBM 128
#define GBN 128
#define GBK 16
#define G_STR 20                      // floats per row (16 used); float2 pitch = 10
#define STG_AL (128 * G_STR)
#define STG_B  (256 * G_STR)
#define STG_SZ (3 * 128 * G_STR)      // 7680 floats per stage
#define GEMM_SMEM (3 * STG_SZ * 4)    // 92160 B

template<int ROPE, int OUT>
__global__ __launch_bounds__(256, 2)
void gemm_pl(const float* __restrict__ Ah, const float* __restrict__ Al,
             const float* __restrict__ Bt, float* __restrict__ C,
             const int* __restrict__ pos) {
    extern __shared__ float sm[];
    const uint32_t smem_base = (uint32_t)__cvta_generic_to_shared(sm);

    const int tid = threadIdx.x;
    const int m0 = blockIdx.y * GBM;
    const int n0 = blockIdx.x * GBN;
    const int w = tid >> 5, lane = tid & 31;
    const int g = lane >> 2, t4 = lane & 3;
    const int wm = w >> 1, wn = w & 1;

    float acc[2][8][4];
#pragma unroll
    for (int i = 0; i < 2; i++)
#pragma unroll
        for (int j = 0; j < 8; j++)
#pragma unroll
            for (int e = 0; e < 4; e++) acc[i][j][e] = 0.f;

    auto issue = [&](int t) {
        int k0 = t * GBK;
        uint32_t base = smem_base + (uint32_t)((t % 3) * STG_SZ) * 4;
#pragma unroll
        for (int it = 0; it < 2; it++) {
            int idx = tid + it * 256;
            int row = idx >> 2;
            int c4  = idx & 3;
            size_t goA = (size_t)(m0 + row) * D_MODEL + k0 + c4 * 4;
            size_t goB = (size_t)(n0 + row) * D_MODEL + k0 + c4 * 4;
            uint32_t so = (uint32_t)(row * G_STR + c4 * 4) * 4;
            cp_async16(base + so, Ah + goA);
            cp_async16(base + STG_AL * 4 + so, Al + goA);
            cp_async16(base + STG_B * 4 + so, Bt + goB);
        }
        cp_commit();
    };

    const int NT = D_MODEL / GBK;
    issue(0);
    issue(1);

    for (int t = 0; t < NT; t++) {
        if (t + 1 < NT) cp_wait<1>(); else cp_wait<0>();
        __syncthreads();

        const float2* A2h = reinterpret_cast<const float2*>(sm + (t % 3) * STG_SZ);
        const float2* A2l = A2h + STG_AL / 2;
        const float2* B2  = A2h + STG_B / 2;

#pragma unroll
        for (int kk = 0; kk < GBK; kk += 8) {
            const int p0 = kk / 2;   // pair base within row (0 or 4)
            uint32_t ah[2][4], al[2][4];
#pragma unroll
            for (int i = 0; i < 2; i++) {
                int row = wm * 32 + i * 16 + g;
                float2 f1 = A2h[row * 10 + p0 + t4];
                float2 f2 = A2h[(row + 8) * 10 + p0 + t4];
                ah[i][0] = fau(f1.x); ah[i][1] = fau(f2.x);
                ah[i][2] = fau(f1.y); ah[i][3] = fau(f2.y);
                float2 g1 = A2l[row * 10 + p0 + t4];
                float2 g2 = A2l[(row + 8) * 10 + p0 + t4];
                al[i][0] = fau(g1.x); al[i][1] = fau(g2.x);
                al[i][2] = fau(g1.y); al[i][3] = fau(g2.y);
            }
#pragma unroll
            for (int j = 0; j < 8; j++) {
                int col = wn * 64 + j * 8 + g;
                float2 fb = B2[col * 10 + p0 + t4];
                uint32_t bh0 = fau(fb.x), bh1 = fau(fb.y);
#pragma unroll
                for (int i = 0; i < 2; i++) {
                    mma_tf32(acc[i][j], ah[i], bh0, bh1);
                    mma_tf32(acc[i][j], al[i], bh0, bh1);
                }
            }
        }

        if (t + 2 < NT) issue(t + 2);
    }

    // epilogue
    float invf[8];
    if (ROPE) {
#pragma unroll
        for (int j = 0; j < 8; j++) {
            int p = ((wn * 64 + j * 8 + 2 * t4) & 63) >> 1;
            invf[j] = powf(10000.0f, -(float)(2 * p) / (float)D_K);
        }
    }
#pragma unroll
    for (int i = 0; i < 2; i++) {
        int r1 = m0 + wm * 32 + i * 16 + g;
        int r2 = r1 + 8;
        float p1 = 0.f, p2 = 0.f;
        if (ROPE) { p1 = (float)pos[r1]; p2 = (float)pos[r2]; }
#pragma unroll
        for (int j = 0; j < 8; j++) {
            int c = n0 + wn * 64 + j * 8 + 2 * t4;
            float v0 = acc[i][j][0], v1 = acc[i][j][1];
            float v2 = acc[i][j][2], v3 = acc[i][j][3];
            if (ROPE) {
                float s, cs;
                sincosf(p1 * invf[j], &s, &cs);
                float u0 = v0 * cs - v1 * s, u1 = v0 * s + v1 * cs;
                v0 = u0; v1 = u1;
                sincosf(p2 * invf[j], &s, &cs);
                float u2 = v2 * cs - v3 * s, u3 = v2 * s + v3 * cs;
                v2 = u2; v3 = u3;
            }
            if (OUT == 0) {
                *reinterpret_cast<float2*>(&C[(size_t)r1 * D_MODEL + c]) = make_float2(v0, v1);
                *reinterpret_cast<float2*>(&C[(size_t)r2 * D_MODEL + c]) = make_float2(v2, v3);
            } else if (OUT == 1) {
                // K: tf32 + column-pair permutation
                int d0 = kperm(c), d1 = kperm(c + 1);
                C[(size_t)r1 * D_MODEL + d0] = tf32r(v0);
                C[(size_t)r1 * D_MODEL + d1] = tf32r(v1);
                C[(size_t)r2 * D_MODEL + d0] = tf32r(v2);
                C[(size_t)r2 * D_MODEL + d1] = tf32r(v3);
            } else {
                // V: tf32 + row-pair interleave: row r -> pair (r/8)*4 + (r%8)%4, elem (r%8)/4
                int pg1 = (r1 >> 3) * 4 + (g & 3);
                int pg2 = pg1 + 4;
                int e = g >> 2;
                size_t b1 = (size_t)pg1 * 2048 + e;
                size_t b2 = (size_t)pg2 * 2048 + e;
                C[b1 + (size_t)c * 2]       = tf32r(v0);
                C[b1 + (size_t)(c + 1) * 2] = tf32r(v1);
                C[b2 + (size_t)c * 2]       = tf32r(v2);
                C[b2 + (size_t)(c + 1) * 2] = tf32r(v3);
            }
        }
    }
}

// ============ Flash attention, LDS.64 packed K/V, cp.async double-buffered ============
#define AQ 128
#define AK 64
#define KS_STR 72          // floats per K row (64 used); float2 pitch 36
#define VP_STR 144         // floats per V pair-row (128 used); float2 pitch 72
#define PS_STR 68
#define K_STAGE (AK * KS_STR)          // 4608 floats
#define V_STAGE (32 * VP_STR)          // 4608 floats
#define ATTN_SMEM ((2 * K_STAGE + 2 * V_STAGE + AQ * PS_STR) * 4)

__global__ __launch_bounds__(256, 2)
void attn_mma_kernel(const float* __restrict__ Q, const float* __restrict__ K,
                     const float* __restrict__ V, float* __restrict__ O) {
    extern __shared__ float sm[];
    float* Kb = sm;
    float* Vb = sm + 2 * K_STAGE;
    float* Ps = sm + 2 * K_STAGE + 2 * V_STAGE;

    const int h   = blockIdx.y;
    const int q0  = (gridDim.x - 1 - blockIdx.x) * AQ;
    const int tid = threadIdx.x;
    const int w = tid >> 5, lane = tid & 31;
    const int g = lane >> 2, t4 = lane & 3;
    const int wrow = q0 + w * 16;

    const uint32_t smem_base = (uint32_t)__cvta_generic_to_shared(sm);

    uint32_t qh[8][4];
    {
        const float* qb = Q + (size_t)wrow * D_MODEL + h * D_K;
#pragma unroll
        for (int kc = 0; kc < 8; kc++) {
            int c0 = kc * 8 + t4;
            qh[kc][0] = fau(tf32r(qb[(size_t)g * D_MODEL + c0] * 0.125f));
            qh[kc][1] = fau(tf32r(qb[(size_t)(g + 8) * D_MODEL + c0] * 0.125f));
            qh[kc][2] = fau(tf32r(qb[(size_t)g * D_MODEL + c0 + 4] * 0.125f));
            qh[kc][3] = fau(tf32r(qb[(size_t)(g + 8) * D_MODEL + c0 + 4] * 0.125f));
        }
    }

    float o[8][4];
#pragma unroll
    for (int j = 0; j < 8; j++)
#pragma unroll
        for (int e = 0; e < 4; e++) o[j][e] = 0.f;
    float m_a = -1e30f, m_b = -1e30f, l_a = 0.f, l_b = 0.f;

    const int nt = (q0 + AQ) / AK;

    auto issue_tile = [&](int t) {
        int kv0 = t * AK;
        int st  = t & 1;
        uint32_t kdst = smem_base + (st * K_STAGE) * 4;
        uint32_t vdst = smem_base + (2 * K_STAGE + st * V_STAGE) * 4;
        // K: 64 rows x 16 chunks
        {
            int r = tid >> 2, c4 = tid & 3;   // 256 threads: 64 rows x 4 -> 4 iter over c4
#pragma unroll
            for (int it = 0; it < 4; it++) {
                int cc = c4 + it * 4;
                const float* kg = &K[(size_t)(kv0 + r) * D_MODEL + h * D_K + cc * 4];
                cp_async16(kdst + (r * KS_STR + cc * 4) * 4, kg);
            }
        }
        // V: 32 pair-rows x 32 chunks
        {
            int r = tid >> 3, cc = tid & 7;   // 256 threads: 32 rows x 8 -> 4 iter
#pragma unroll
            for (int it = 0; it < 4; it++) {
                int c = cc + it * 8;
                const float* vg = &V[(size_t)(kv0 / 2 + r) * 2048 + h * 128 + c * 4];
                cp_async16(vdst + (r * VP_STR + c * 4) * 4, vg);
            }
        }
        cp_commit();
    };

    issue_tile(0);

    for (int t = 0; t < nt; t++) {
        if (t + 1 < nt) {
            issue_tile(t + 1);
            cp_wait<1>();
        } else {
            cp_wait<0>();
        }
        __syncthreads();

        const int kv0 = t * AK;
        const float2* K2 = reinterpret_cast<const float2*>(Kb + (t & 1) * K_STAGE);
        const float2* V2 = reinterpret_cast<const float2*>(Vb + (t & 1) * V_STAGE);

        if (kv0 <= wrow + 15) {
            float s[8][4];
#pragma unroll
            for (int j = 0; j < 8; j++)
#pragma unroll
                for (int e = 0; e < 4; e++) s[j][e] = 0.f;

#pragma unroll
            for (int kc = 0; kc < 8; kc++) {
#pragma unroll
                for (int j = 0; j < 8; j++) {
                    float2 f = K2[(j * 8 + g) * 36 + kc * 4 + t4];
                    mma_tf32(s[j], qh[kc], fau(f.x), fau(f.y));
                }
            }

            if (kv0 + AK - 1 > wrow) {
#pragma unroll
                for (int j = 0; j < 8; j++) {
                    int col = kv0 + j * 8 + 2 * t4;
                    int ra = wrow + g, rb2 = wrow + g + 8;
                    if (col > ra)      s[j][0] = -1e30f;
                    if (col + 1 > ra)  s[j][1] = -1e30f;
                    if (col > rb2)     s[j][2] = -1e30f;
                    if (col + 1 > rb2) s[j][3] = -1e30f;
                }
            }

            float mx_a = -1e30f, mx_b = -1e30f;
#pragma unroll
            for (int j = 0; j < 8; j++) {
                mx_a = fmaxf(mx_a, fmaxf(s[j][0], s[j][1]));
                mx_b = fmaxf(mx_b, fmaxf(s[j][2], s[j][3]));
            }
            mx_a = fmaxf(mx_a, __shfl_xor_sync(0xffffffffu, mx_a, 1));
            mx_a = fmaxf(mx_a, __shfl_xor_sync(0xffffffffu, mx_a, 2));
            mx_b = fmaxf(mx_b, __shfl_xor_sync(0xffffffffu, mx_b, 1));
            mx_b = fmaxf(mx_b, __shfl_xor_sync(0xffffffffu, mx_b, 2));
            float nm_a = fmaxf(m_a, mx_a), nm_b = fmaxf(m_b, mx_b);
            float al_a = __expf(m_a - nm_a), al_b = __expf(m_b - nm_b);
            m_a = nm_a; m_b = nm_b;

            float sum_a = 0.f, sum_b = 0.f;
#pragma unroll
            for (int j = 0; j < 8; j++) {
                float p0 = __expf(s[j][0] - m_a);
                float p1 = __expf(s[j][1] - m_a);
                float p2 = __expf(s[j][2] - m_b);
                float p3 = __expf(s[j][3] - m_b);
                sum_a += p0 + p1;
                sum_b += p2 + p3;
                o[j][0] *= al_a; o[j][1] *= al_a;
                o[j][2] *= al_b; o[j][3] *= al_b;
                float2 pa = make_float2(tf32r(p0), tf32r(p1));
                float2 pb = make_float2(tf32r(p2), tf32r(p3));
                *reinterpret_cast<float2*>(&Ps[(w * 16 + g) * PS_STR + j * 8 + 2 * t4]) = pa;
                *reinterpret_cast<float2*>(&Ps[(w * 16 + g + 8) * PS_STR + j * 8 + 2 * t4]) = pb;
            }
            sum_a += __shfl_xor_sync(0xffffffffu, sum_a, 1);
            sum_a += __shfl_xor_sync(0xffffffffu, sum_a, 2);
            sum_b += __shfl_xor_sync(0xffffffffu, sum_b, 1);
            sum_b += __shfl_xor_sync(0xffffffffu, sum_b, 2);
            l_a = l_a * al_a + sum_a;
            l_b = l_b * al_b + sum_b;
            __syncwarp();

#pragma unroll
            for (int kc = 0; kc < 8; kc++) {
                uint32_t pa[4];
                int pr = (w * 16 + g) * PS_STR + kc * 8 + t4;
                pa[0] = fau(Ps[pr]);
                pa[1] = fau(Ps[pr + 8 * PS_STR]);
                pa[2] = fau(Ps[pr + 4]);
                pa[3] = fau(Ps[pr + 8 * PS_STR + 4]);
#pragma unroll
                for (int j = 0; j < 8; j++) {
                    float2 fv = V2[(kc * 4 + t4) * 72 + j * 8 + g];
                    mma_tf32(o[j], pa, fau(fv.x), fau(fv.y));
                }
            }
        }
        __syncthreads();
    }

    float ia = 1.0f / l_a, ib = 1.0f / l_b;
#pragma unroll
    for (int j = 0; j < 8; j++) {
        int c = h * D_K + j * 8 + 2 * t4;
        float2 v0 = make_float2(o[j][0] * ia, o[j][1] * ia);
        float2 v1 = make_float2(o[j][2] * ib, o[j][3] * ib);
        *reinterpret_cast<float2*>(&O[(size_t)(wrow + g) * D_MODEL + c]) = v0;
        *reinterpret_cast<float2*>(&O[(size_t)(wrow + g + 8) * D_MODEL + c]) = v1;
    }
}

// ---------------- launcher ----------------
extern "C" void kernel_launch(void* const* d_in, const int* in_sizes, int n_in,
                              void* d_out, int out_size) {
    const float* x  = (const float*)d_in[0];
    const float* Wq = (const float*)d_in[1];
    const float* Wk = (const float*)d_in[2];
    const float* Wv = (const float*)d_in[3];
    const float* Wo = (const float*)d_in[4];
    const int*  pos = (const int*)d_in[5];
    float* out = (float*)d_out;

    float *Qp, *Kp, *Vp, *Ap, *XH, *XL, *W1, *W2, *W3;
    cudaGetSymbolAddress((void**)&Qp, g_Q);
    cudaGetSymbolAddress((void**)&Kp, g_K);
    cudaGetSymbolAddress((void**)&Vp, g_V);
    cudaGetSymbolAddress((void**)&Ap, g_AT);
    cudaGetSymbolAddress((void**)&XH, g_XH);
    cudaGetSymbolAddress((void**)&XL, g_XL);
    cudaGetSymbolAddress((void**)&W1, g_W1);
    cudaGetSymbolAddress((void**)&W2, g_W2);
    cudaGetSymbolAddress((void**)&W3, g_W3);

    cudaFuncSetAttribute(gemm_pl<1,0>, cudaFuncAttributeMaxDynamicSharedMemorySize, GEMM_SMEM);
    cudaFuncSetAttribute(gemm_pl<1,1>, cudaFuncAttributeMaxDynamicSharedMemorySize, GEMM_SMEM);
    cudaFuncSetAttribute(gemm_pl<0,2>, cudaFuncAttributeMaxDynamicSharedMemorySize, GEMM_SMEM);
    cudaFuncSetAttribute(gemm_pl<0,0>, cudaFuncAttributeMaxDynamicSharedMemorySize, GEMM_SMEM);
    cudaFuncSetAttribute(attn_mma_kernel, cudaFuncAttributeMaxDynamicSharedMemorySize, ATTN_SMEM);

    const int NX4 = S_LEN * D_MODEL / 4;
    const int NW4 = D_MODEL * D_MODEL / 4;
    dim3 ggrid(D_MODEL / GBN, S_LEN / GBM);
    dim3 agrid(S_LEN / AQ, NUM_HEADS);

    // prepasses: split activations, round all three projection weights (one launch)
    split_kernel<<<(NX4 + 255) / 256, 256>>>((const float4*)x, XH, XL, NX4);
    round3_kernel<<<(NW4 + 255) / 256, 256>>>((const float4*)Wq, (const float4*)Wk,
                                              (const float4*)Wv, W1, W2, W3, NW4);

    gemm_pl<1,0><<<ggrid, 256, GEMM_SMEM>>>(XH, XL, W1, Qp, pos);  // Q (+RoPE)
    gemm_pl<1,1><<<ggrid, 256, GEMM_SMEM>>>(XH, XL, W2, Kp, pos);  // K (+RoPE, K-layout)
    gemm_pl<0,2><<<ggrid, 256, GEMM_SMEM>>>(XH, XL, W3, Vp, pos);  // V (V-layout)

    attn_mma_kernel<<<agrid, 256, ATTN_SMEM>>>(Qp, Kp, Vp, Ap);

    split_kernel<<<(NX4 + 255) / 256, 256>>>((const float4*)Ap, XH, XL, NX4);
    round1_kernel<<<(NW4 + 255) / 256, 256>>>((const float4*)Wo, W3, NW4);
    gemm_pl<0,0><<<ggrid, 256, GEMM_SMEM>>>(XH, XL, W3, out, pos);
}

// round 15
// speedup vs baseline: 1.1609x; 1.1609x over previous
#include <cuda_runtime.h>
#include <math.h>
#include <stdint.h>

#define S_LEN 4096
#define D_MODEL 1024
#define NUM_HEADS 16
#define D_K 64

// ---------------- scratch (no allocs allowed) ----------------
__device__ float g_Q[S_LEN * D_MODEL];
__device__ float g_K[S_LEN * D_MODEL];
__device__ float g_V[S_LEN * D_MODEL];
__device__ float g_AT[S_LEN * D_MODEL];
__device__ float2 g_XHL[S_LEN * D_MODEL];  // interleaved {hi,lo} activation plane
__device__ float g_W1[D_MODEL * D_MODEL];  // tf32 Wq, k-pair permuted
__device__ float g_W2[D_MODEL * D_MODEL];  // tf32 Wk
__device__ float g_W3[D_MODEL * D_MODEL];  // tf32 Wv / Wo

// ---------------- helpers ----------------
__device__ __forceinline__ float tf32r(float x) {
    uint32_t u;
    asm("cvt.rna.tf32.f32 %0, %1;" : "=r"(u) : "f"(x));
    return __uint_as_float(u);
}
__device__ __forceinline__ uint32_t fau(float x) { return __float_as_uint(x); }

__device__ __forceinline__ void mma_tf32(float* d, const uint32_t* a, uint32_t b0, uint32_t b1) {
    asm volatile(
        "mma.sync.aligned.m16n8k8.row.col.f32.tf32.tf32.f32 "
        "{%0,%1,%2,%3}, {%4,%5,%6,%7}, {%8,%9}, {%0,%1,%2,%3};"
        : "+f"(d[0]), "+f"(d[1]), "+f"(d[2]), "+f"(d[3])
        : "r"(a[0]), "r"(a[1]), "r"(a[2]), "r"(a[3]), "r"(b0), "r"(b1));
}

__device__ __forceinline__ void cp_async16(uint32_t smem_addr, const void* gptr) {
    asm volatile("cp.async.cg.shared.global [%0], [%1], 16;\n"
                 :: "r"(smem_addr), "l"(gptr));
}
__device__ __forceinline__ void cp_commit() {
    asm volatile("cp.async.commit_group;\n" ::: "memory");
}
template<int N>
__device__ __forceinline__ void cp_wait() {
    asm volatile("cp.async.wait_group %0;\n" :: "n"(N) : "memory");
}

// ---------------- prepasses ----------------
// Activations: interleaved {hi, lo} float2 per element, natural k order.
__global__ void split_kernel(const float4* __restrict__ src, float2* __restrict__ hl, int n4) {
    int i = blockIdx.x * blockDim.x + threadIdx.x;
    if (i >= n4) return;
    float4 v = src[i];
    int b = i * 4;
    float h0 = tf32r(v.x), h1 = tf32r(v.y), h2 = tf32r(v.z), h3 = tf32r(v.w);
    hl[b]     = make_float2(h0, tf32r(v.x - h0));
    hl[b + 1] = make_float2(h1, tf32r(v.y - h1));
    hl[b + 2] = make_float2(h2, tf32r(v.z - h2));
    hl[b + 3] = make_float2(h3, tf32r(v.w - h3));
}

// Weights: tf32-rounded, k-pair permuted within each 8-group
// (k -> (k%4)*2 + k/4, so (k, k+4) land in adjacent floats).
__global__ void round3_kernel(const float4* __restrict__ s1, const float4* __restrict__ s2,
                              const float4* __restrict__ s3, float* __restrict__ d1,
                              float* __restrict__ d2, float* __restrict__ d3, int n4) {
    int i = blockIdx.x * blockDim.x + threadIdx.x;
    if (i >= n4) return;
    int b = i * 4;
    int d = (b & ~7) | ((b & 4) ? 1 : 0);
    float4 v = s1[i];
    d1[d] = tf32r(v.x); d1[d + 2] = tf32r(v.y); d1[d + 4] = tf32r(v.z); d1[d + 6] = tf32r(v.w);
    v = s2[i];
    d2[d] = tf32r(v.x); d2[d + 2] = tf32r(v.y); d2[d + 4] = tf32r(v.z); d2[d + 6] = tf32r(v.w);
    v = s3[i];
    d3[d] = tf32r(v.x); d3[d + 2] = tf32r(v.y); d3[d + 4] = tf32r(v.z); d3[d + 6] = tf32r(v.w);
}

__global__ void round1_kernel(const float4* __restrict__ src, float* __restrict__ dst, int n4) {
    int i = blockIdx.x * blockDim.x + threadIdx.x;
    if (i >= n4) return;
    int b = i * 4;
    int d = (b & ~7) | ((b & 4) ? 1 : 0);
    float4 v = src[i];
    dst[d] = tf32r(v.x); dst[d + 2] = tf32r(v.y); dst[d + 4] = tf32r(v.z); dst[d + 6] = tf32r(v.w);
}

// ---------------- 2xTF32 pipelined GEMM, LDS.64 operand loads ----------------
// A: interleaved {hi,lo} float2 plane (natural k). B: tf32, k-pair permuted.
// Smem per stage: A 128 rows x 40 floats (20 float2, 16 used) = 5120 floats,
//                 B 128 rows x 24 floats (16 used)            = 3072 floats.
#define GBM 128
#define GBN 128
#define GBK 16
#define STG_BO 5120                   // float offset of B within stage
#define STG_SZ 8192                   // floats per stage
#define GEMM_SMEM (3 * STG_SZ * 4)    // 98304 B

template<int ROPE, int TFOUT>
__global__ __launch_bounds__(256, 2)
void gemm_pl(const float2* __restrict__ Ahl, const float* __restrict__ Bt,
             float* __restrict__ C, const int* __restrict__ pos) {
    extern __shared__ float sm[];
    const uint32_t smem_base = (uint32_t)__cvta_generic_to_shared(sm);

    const int tid = threadIdx.x;
    const int m0 = blockIdx.y * GBM;
    const int n0 = blockIdx.x * GBN;
    const int w = tid >> 5, lane = tid & 31;
    const int g = lane >> 2, t4 = lane & 3;
    const int wm = w >> 1, wn = w & 1;

    float acc[2][8][4];
#pragma unroll
    for (int i = 0; i < 2; i++)
#pragma unroll
        for (int j = 0; j < 8; j++)
#pragma unroll
            for (int e = 0; e < 4; e++) acc[i][j][e] = 0.f;

    auto issue = [&](int t) {
        int k0 = t * GBK;
        uint32_t base = smem_base + (uint32_t)((t % 3) * STG_SZ) * 4;
        // A: 128 rows x 16 float2 = 1024 16B-chunks (2 float2 each)
#pragma unroll
        for (int it = 0; it < 4; it++) {
            int idx = tid + it * 256;
            int row = idx >> 3;
            int ch  = idx & 7;
            const float2* ga = Ahl + (size_t)(m0 + row) * D_MODEL + k0 + ch * 2;
            cp_async16(base + (uint32_t)(row * 40 + ch * 4) * 4, ga);
        }
        // B: 128 rows x 16 floats = 512 16B-chunks
#pragma unroll
        for (int it = 0; it < 2; it++) {
            int idx = tid + it * 256;
            int row = idx >> 2;
            int ch  = idx & 3;
            const float* gb = Bt + (size_t)(n0 + row) * D_MODEL + k0 + ch * 4;
            cp_async16(base + (uint32_t)(STG_BO + row * 24 + ch * 4) * 4, gb);
        }
        cp_commit();
    };

    const int NT = D_MODEL / GBK;
    issue(0);
    issue(1);

    for (int t = 0; t < NT; t++) {
        if (t + 1 < NT) cp_wait<1>(); else cp_wait<0>();
        __syncthreads();

        const float2* A2 = reinterpret_cast<const float2*>(sm + (t % 3) * STG_SZ);
        const float2* B2 = reinterpret_cast<const float2*>(sm + (t % 3) * STG_SZ + STG_BO);

#pragma unroll
        for (int kk = 0; kk < GBK; kk += 8) {
            const int p0 = kk >> 1;           // B pair base: 0 or 4
            uint32_t ah[2][4], al[2][4];
#pragma unroll
            for (int i = 0; i < 2; i++) {
                int row = wm * 32 + i * 16 + g;
                float2 f1 = A2[row * 20 + kk + t4];
                float2 f2 = A2[row * 20 + kk + t4 + 4];
                float2 f3 = A2[(row + 8) * 20 + kk + t4];
                float2 f4 = A2[(row + 8) * 20 + kk + t4 + 4];
                ah[i][0] = fau(f1.x); ah[i][1] = fau(f3.x);
                ah[i][2] = fau(f2.x); ah[i][3] = fau(f4.x);
                al[i][0] = fau(f1.y); al[i][1] = fau(f3.y);
                al[i][2] = fau(f2.y); al[i][3] = fau(f4.y);
            }
#pragma unroll
            for (int j = 0; j < 8; j++) {
                int col = wn * 64 + j * 8 + g;
                float2 fb = B2[col * 12 + p0 + t4];
                uint32_t bh0 = fau(fb.x), bh1 = fau(fb.y);
#pragma unroll
                for (int i = 0; i < 2; i++) {
                    mma_tf32(acc[i][j], ah[i], bh0, bh1);
                    mma_tf32(acc[i][j], al[i], bh0, bh1);
                }
            }
        }

        if (t + 2 < NT) issue(t + 2);
    }

    // epilogue (R12-proven); ROPE / TFOUT compile-time
    float invf[8];
    if (ROPE) {
#pragma unroll
        for (int j = 0; j < 8; j++) {
            int p = ((wn * 64 + j * 8 + 2 * t4) & 63) >> 1;
            invf[j] = powf(10000.0f, -(float)(2 * p) / (float)D_K);
        }
    }
#pragma unroll
    for (int i = 0; i < 2; i++) {
        int r1 = m0 + wm * 32 + i * 16 + g;
        int r2 = r1 + 8;
        float p1 = 0.f, p2 = 0.f;
        if (ROPE) { p1 = (float)pos[r1]; p2 = (float)pos[r2]; }
#pragma unroll
        for (int j = 0; j < 8; j++) {
            int c = n0 + wn * 64 + j * 8 + 2 * t4;
            float v0 = acc[i][j][0], v1 = acc[i][j][1];
            float v2 = acc[i][j][2], v3 = acc[i][j][3];
            if (ROPE) {
                float s, cs;
                sincosf(p1 * invf[j], &s, &cs);
                float u0 = v0 * cs - v1 * s, u1 = v0 * s + v1 * cs;
                v0 = u0; v1 = u1;
                sincosf(p2 * invf[j], &s, &cs);
                float u2 = v2 * cs - v3 * s, u3 = v2 * s + v3 * cs;
                v2 = u2; v3 = u3;
            }
            if (TFOUT) {
                v0 = tf32r(v0); v1 = tf32r(v1); v2 = tf32r(v2); v3 = tf32r(v3);
            }
            *reinterpret_cast<float2*>(&C[(size_t)r1 * D_MODEL + c]) = make_float2(v0, v1);
            *reinterpret_cast<float2*>(&C[(size_t)r2 * D_MODEL + c]) = make_float2(v2, v3);
        }
    }
}

// ============ Flash attention, tf32 mma, cp.async double-buffered (R12-proven) ============
#define AQ 128
#define AK 64
#define KS_STR 68
#define V_STR  72
#define PS_STR 68
#define K_STAGE (AK * KS_STR)
#define V_STAGE (AK * V_STR)
#define ATTN_SMEM ((2 * K_STAGE + 2 * V_STAGE + AQ * PS_STR) * 4)

__global__ __launch_bounds__(256, 2)
void attn_mma_kernel(const float* __restrict__ Q, const float* __restrict__ K,
                     const float* __restrict__ V, float* __restrict__ O) {
    extern __shared__ float sm[];
    float* Kb = sm;
    float* Vb = sm + 2 * K_STAGE;
    float* Ps = sm + 2 * K_STAGE + 2 * V_STAGE;

    const int h   = blockIdx.y;
    const int q0  = (gridDim.x - 1 - blockIdx.x) * AQ;
    const int tid = threadIdx.x;
    const int w = tid >> 5, lane = tid & 31;
    const int g = lane >> 2, t4 = lane & 3;
    const int wrow = q0 + w * 16;

    const uint32_t smem_base = (uint32_t)__cvta_generic_to_shared(sm);
    const int lr  = tid >> 4;
    const int lc4 = tid & 15;

    uint32_t qh[8][4];
    {
        const float* qb = Q + (size_t)wrow * D_MODEL + h * D_K;
#pragma unroll
        for (int kc = 0; kc < 8; kc++) {
            int c0 = kc * 8 + t4;
            qh[kc][0] = fau(tf32r(qb[(size_t)g * D_MODEL + c0] * 0.125f));
            qh[kc][1] = fau(tf32r(qb[(size_t)(g + 8) * D_MODEL + c0] * 0.125f));
            qh[kc][2] = fau(tf32r(qb[(size_t)g * D_MODEL + c0 + 4] * 0.125f));
            qh[kc][3] = fau(tf32r(qb[(size_t)(g + 8) * D_MODEL + c0 + 4] * 0.125f));
        }
    }

    float o[8][4];
#pragma unroll
    for (int j = 0; j < 8; j++)
#pragma unroll
        for (int e = 0; e < 4; e++) o[j][e] = 0.f;
    float m_a = -1e30f, m_b = -1e30f, l_a = 0.f, l_b = 0.f;

    const int nt = (q0 + AQ) / AK;

    auto issue_tile = [&](int t) {
        int kv0 = t * AK;
        int st  = t & 1;
        uint32_t kdst = smem_base + (st * K_STAGE) * 4;
        uint32_t vdst = smem_base + (2 * K_STAGE + st * V_STAGE) * 4;
#pragma unroll
        for (int it = 0; it < 4; it++) {
            int r  = lr + it * 16;
            const float* kg = &K[(size_t)(kv0 + r) * D_MODEL + h * D_K + lc4 * 4];
            const float* vg = &V[(size_t)(kv0 + r) * D_MODEL + h * D_K + lc4 * 4];
            cp_async16(kdst + (r * KS_STR + lc4 * 4) * 4, kg);
            cp_async16(vdst + (r * V_STR + lc4 * 4) * 4, vg);
        }
        cp_commit();
    };

    issue_tile(0);

    for (int t = 0; t < nt; t++) {
        if (t + 1 < nt) {
            issue_tile(t + 1);
            cp_wait<1>();
        } else {
            cp_wait<0>();
        }
        __syncthreads();

        const int kv0 = t * AK;
        const float* Ks = Kb + (t & 1) * K_STAGE;
        const float* Vs = Vb + (t & 1) * V_STAGE;

        if (kv0 <= wrow + 15) {
            float s[8][4];
#pragma unroll
            for (int j = 0; j < 8; j++)
#pragma unroll
                for (int e = 0; e < 4; e++) s[j][e] = 0.f;

#pragma unroll
            for (int kc = 0; kc < 8; kc++) {
#pragma unroll
                for (int j = 0; j < 8; j++) {
                    int rb = (j * 8 + g) * KS_STR + kc * 8 + t4;
                    uint32_t b0 = fau(Ks[rb]);
                    uint32_t b1 = fau(Ks[rb + 4]);
                    mma_tf32(s[j], qh[kc], b0, b1);
                }
            }

            if (kv0 + AK - 1 > wrow) {
#pragma unroll
                for (int j = 0; j < 8; j++) {
                    int col = kv0 + j * 8 + 2 * t4;
                    int ra = wrow + g, rb2 = wrow + g + 8;
                    if (col > ra)      s[j][0] = -1e30f;
                    if (col + 1 > ra)  s[j][1] = -1e30f;
                    if (col > rb2)     s[j][2] = -1e30f;
                    if (col + 1 > rb2) s[j][3] = -1e30f;
                }
            }

            float mx_a = -1e30f, mx_b = -1e30f;
#pragma unroll
            for (int j = 0; j < 8; j++) {
                mx_a = fmaxf(mx_a, fmaxf(s[j][0], s[j][1]));
                mx_b = fmaxf(mx_b, fmaxf(s[j][2], s[j][3]));
            }
            mx_a = fmaxf(mx_a, __shfl_xor_sync(0xffffffffu, mx_a, 1));
            mx_a = fmaxf(mx_a, __shfl_xor_sync(0xffffffffu, mx_a, 2));
            mx_b = fmaxf(mx_b, __shfl_xor_sync(0xffffffffu, mx_b, 1));
            mx_b = fmaxf(mx_b, __shfl_xor_sync(0xffffffffu, mx_b, 2));
            float nm_a = fmaxf(m_a, mx_a), nm_b = fmaxf(m_b, mx_b);
            float al_a = __expf(m_a - nm_a), al_b = __expf(m_b - nm_b);
            m_a = nm_a; m_b = nm_b;

            float sum_a = 0.f, sum_b = 0.f;
#pragma unroll
            for (int j = 0; j < 8; j++) {
                float p0 = __expf(s[j][0] - m_a);
                float p1 = __expf(s[j][1] - m_a);
                float p2 = __expf(s[j][2] - m_b);
                float p3 = __expf(s[j][3] - m_b);
                sum_a += p0 + p1;
                sum_b += p2 + p3;
                o[j][0] *= al_a; o[j][1] *= al_a;
                o[j][2] *= al_b; o[j][3] *= al_b;
                float2 pa = make_float2(tf32r(p0), tf32r(p1));
                float2 pb = make_float2(tf32r(p2), tf32r(p3));
                *reinterpret_cast<float2*>(&Ps[(w * 16 + g) * PS_STR + j * 8 + 2 * t4]) = pa;
                *reinterpret_cast<float2*>(&Ps[(w * 16 + g + 8) * PS_STR + j * 8 + 2 * t4]) = pb;
            }
            sum_a += __shfl_xor_sync(0xffffffffu, sum_a, 1);
            sum_a += __shfl_xor_sync(0xffffffffu, sum_a, 2);
            sum_b += __shfl_xor_sync(0xffffffffu, sum_b, 1);
            sum_b += __shfl_xor_sync(0xffffffffu, sum_b, 2);
            l_a = l_a * al_a + sum_a;
            l_b = l_b * al_b + sum_b;
            __syncwarp();

#pragma unroll
            for (int kc = 0; kc < 8; kc++) {
                uint32_t pa[4];
                int pr = (w * 16 + g) * PS_STR + kc * 8 + t4;
                pa[0] = fau(Ps[pr]);
                pa[1] = fau(Ps[pr + 8 * PS_STR]);
                pa[2] = fau(Ps[pr + 4]);
                pa[3] = fau(Ps[pr + 8 * PS_STR + 4]);
#pragma unroll
                for (int j = 0; j < 8; j++) {
                    int vb = (kc * 8 + t4) * V_STR + j * 8 + g;
                    uint32_t b0 = fau(Vs[vb]);
                    uint32_t b1 = fau(Vs[vb + 4 * V_STR]);
                    mma_tf32(o[j], pa, b0, b1);
                }
            }
        }
        __syncthreads();
    }

    float ia = 1.0f / l_a, ib = 1.0f / l_b;
#pragma unroll
    for (int j = 0; j < 8; j++) {
        int c = h * D_K + j * 8 + 2 * t4;
        float2 v0 = make_float2(o[j][0] * ia, o[j][1] * ia);
        float2 v1 = make_float2(o[j][2] * ib, o[j][3] * ib);
        *reinterpret_cast<float2*>(&O[(size_t)(wrow + g) * D_MODEL + c]) = v0;
        *reinterpret_cast<float2*>(&O[(size_t)(wrow + g + 8) * D_MODEL + c]) = v1;
    }
}

// ---------------- launcher ----------------
extern "C" void kernel_launch(void* const* d_in, const int* in_sizes, int n_in,
                              void* d_out, int out_size) {
    const float* x  = (const float*)d_in[0];
    const float* Wq = (const float*)d_in[1];
    const float* Wk = (const float*)d_in[2];
    const float* Wv = (const float*)d_in[3];
    const float* Wo = (const float*)d_in[4];
    const int*  pos = (const int*)d_in[5];
    float* out = (float*)d_out;

    float *Qp, *Kp, *Vp, *Ap, *W1, *W2, *W3;
    float2* XHL;
    cudaGetSymbolAddress((void**)&Qp, g_Q);
    cudaGetSymbolAddress((void**)&Kp, g_K);
    cudaGetSymbolAddress((void**)&Vp, g_V);
    cudaGetSymbolAddress((void**)&Ap, g_AT);
    cudaGetSymbolAddress((void**)&XHL, g_XHL);
    cudaGetSymbolAddress((void**)&W1, g_W1);
    cudaGetSymbolAddress((void**)&W2, g_W2);
    cudaGetSymbolAddress((void**)&W3, g_W3);

    cudaFuncSetAttribute(gemm_pl<1,0>, cudaFuncAttributeMaxDynamicSharedMemorySize, GEMM_SMEM);
    cudaFuncSetAttribute(gemm_pl<1,1>, cudaFuncAttributeMaxDynamicSharedMemorySize, GEMM_SMEM);
    cudaFuncSetAttribute(gemm_pl<0,1>, cudaFuncAttributeMaxDynamicSharedMemorySize, GEMM_SMEM);
    cudaFuncSetAttribute(gemm_pl<0,0>, cudaFuncAttributeMaxDynamicSharedMemorySize, GEMM_SMEM);
    cudaFuncSetAttribute(attn_mma_kernel, cudaFuncAttributeMaxDynamicSharedMemorySize, ATTN_SMEM);

    const int NX4 = S_LEN * D_MODEL / 4;
    const int NW4 = D_MODEL * D_MODEL / 4;
    dim3 ggrid(D_MODEL / GBN, S_LEN / GBM);
    dim3 agrid(S_LEN / AQ, NUM_HEADS);

    // prepasses
    split_kernel<<<(NX4 + 255) / 256, 256>>>((const float4*)x, XHL, NX4);
    round3_kernel<<<(NW4 + 255) / 256, 256>>>((const float4*)Wq, (const float4*)Wk,
                                              (const float4*)Wv, W1, W2, W3, NW4);

    gemm_pl<1,0><<<ggrid, 256, GEMM_SMEM>>>(XHL, W1, Qp, pos);  // Q (+RoPE)
    gemm_pl<1,1><<<ggrid, 256, GEMM_SMEM>>>(XHL, W2, Kp, pos);  // K (+RoPE, tf32 out)
    gemm_pl<0,1><<<ggrid, 256, GEMM_SMEM>>>(XHL, W3, Vp, pos);  // V (tf32 out)

    attn_mma_kernel<<<agrid, 256, ATTN_SMEM>>>(Qp, Kp, Vp, Ap);

    split_kernel<<<(NX4 + 255) / 256, 256>>>((const float4*)Ap, XHL, NX4);
    round1_kernel<<<(NW4 + 255) / 256, 256>>>((const float4*)Wo, W3, NW4);
    gemm_pl<0,0><<<ggrid, 256, GEMM_SMEM>>>(XHL, W3, out, pos);
}

// round 16
// speedup vs baseline: 1.2624x; 1.0874x over previous
#include <cuda_runtime.h>
#include <math.h>
#include <stdint.h>

#define S_LEN 4096
#define D_MODEL 1024
#define NUM_HEADS 16
#define D_K 64

// ---------------- scratch (no allocs allowed) ----------------
__device__ float g_Q[S_LEN * D_MODEL];
__device__ float g_K[S_LEN * D_MODEL];
__device__ float g_V[S_LEN * D_MODEL];
__device__ float g_XH[S_LEN * D_MODEL];      // hi plane of activations
__device__ float g_XL[S_LEN * D_MODEL];      // lo plane of activations
__device__ float g_W123[3 * D_MODEL * D_MODEL]; // tf32 Wq|Wk|Wv merged (then Wo reuses)

// ---------------- helpers ----------------
__device__ __forceinline__ float tf32r(float x) {
    uint32_t u;
    asm("cvt.rna.tf32.f32 %0, %1;" : "=r"(u) : "f"(x));
    return __uint_as_float(u);
}
__device__ __forceinline__ uint32_t fau(float x) { return __float_as_uint(x); }

__device__ __forceinline__ void mma_tf32(float* d, const uint32_t* a, uint32_t b0, uint32_t b1) {
    asm volatile(
        "mma.sync.aligned.m16n8k8.row.col.f32.tf32.tf32.f32 "
        "{%0,%1,%2,%3}, {%4,%5,%6,%7}, {%8,%9}, {%0,%1,%2,%3};"
        : "+f"(d[0]), "+f"(d[1]), "+f"(d[2]), "+f"(d[3])
        : "r"(a[0]), "r"(a[1]), "r"(a[2]), "r"(a[3]), "r"(b0), "r"(b1));
}

__device__ __forceinline__ void cp_async16(uint32_t smem_addr, const void* gptr) {
    asm volatile("cp.async.cg.shared.global [%0], [%1], 16;\n"
                 :: "r"(smem_addr), "l"(gptr));
}
__device__ __forceinline__ void cp_commit() {
    asm volatile("cp.async.commit_group;\n" ::: "memory");
}
template<int N>
__device__ __forceinline__ void cp_wait() {
    asm volatile("cp.async.wait_group %0;\n" :: "n"(N) : "memory");
}

// ---------------- prepasses ----------------
__global__ void split_kernel(const float4* __restrict__ src, float4* __restrict__ hi,
                             float4* __restrict__ lo, int n4) {
    int i = blockIdx.x * blockDim.x + threadIdx.x;
    if (i >= n4) return;
    float4 v = src[i];
    float4 h, l;
    h.x = tf32r(v.x); l.x = tf32r(v.x - h.x);
    h.y = tf32r(v.y); l.y = tf32r(v.y - h.y);
    h.z = tf32r(v.z); l.z = tf32r(v.z - h.z);
    h.w = tf32r(v.w); l.w = tf32r(v.w - h.w);
    hi[i] = h; lo[i] = l;
}

// round three weight matrices into one contiguous [3*D_MODEL, D_MODEL] buffer
__global__ void round3_kernel(const float4* __restrict__ s1, const float4* __restrict__ s2,
                              const float4* __restrict__ s3, float4* __restrict__ dst, int n4) {
    int i = blockIdx.x * blockDim.x + threadIdx.x;
    if (i >= n4) return;
    float4 v = s1[i];
    float4 h;
    h.x = tf32r(v.x); h.y = tf32r(v.y); h.z = tf32r(v.z); h.w = tf32r(v.w);
    dst[i] = h;
    v = s2[i];
    h.x = tf32r(v.x); h.y = tf32r(v.y); h.z = tf32r(v.z); h.w = tf32r(v.w);
    dst[i + n4] = h;
    v = s3[i];
    h.x = tf32r(v.x); h.y = tf32r(v.y); h.z = tf32r(v.z); h.w = tf32r(v.w);
    dst[i + 2 * n4] = h;
}

__global__ void round1_kernel(const float4* __restrict__ src, float4* __restrict__ dst, int n4) {
    int i = blockIdx.x * blockDim.x + threadIdx.x;
    if (i >= n4) return;
    float4 v = src[i];
    float4 h;
    h.x = tf32r(v.x); h.y = tf32r(v.y); h.z = tf32r(v.z); h.w = tf32r(v.w);
    dst[i] = h;
}

// ---------------- 2xTF32 pipelined GEMM core (R12-proven mainloop) ----------------
#define GBM 128
#define GBN 128
#define GBK 16
#define G_STR 20
#define STG_AL (128 * G_STR)
#define STG_B  (256 * G_STR)
#define STG_SZ (3 * 128 * G_STR)      // 7680 floats per stage
#define GEMM_SMEM (3 * STG_SZ * 4)    // 92160 B

// Merged QKV GEMM: B is [3*D_MODEL, D_MODEL]; segment routing in epilogue.
__global__ __launch_bounds__(256, 2)
void gemm_qkv(const float* __restrict__ Ah, const float* __restrict__ Al,
              const float* __restrict__ Bt, float* __restrict__ Qo,
              float* __restrict__ Ko, float* __restrict__ Vo,
              const int* __restrict__ pos) {
    extern __shared__ float sm[];
    const uint32_t smem_base = (uint32_t)__cvta_generic_to_shared(sm);

    const int tid = threadIdx.x;
    const int m0 = blockIdx.y * GBM;
    const int n0g = blockIdx.x * GBN;            // global over 3072
    const int seg = blockIdx.x >> 3;             // 0=Q 1=K 2=V
    const int n0 = n0g & (D_MODEL - 1);          // within projection
    const int w = tid >> 5, lane = tid & 31;
    const int g = lane >> 2, t4 = lane & 3;
    const int wm = w >> 1, wn = w & 1;

    float acc[2][8][4];
#pragma unroll
    for (int i = 0; i < 2; i++)
#pragma unroll
        for (int j = 0; j < 8; j++)
#pragma unroll
            for (int e = 0; e < 4; e++) acc[i][j][e] = 0.f;

    auto issue = [&](int t) {
        int k0 = t * GBK;
        uint32_t base = smem_base + (uint32_t)((t % 3) * STG_SZ) * 4;
#pragma unroll
        for (int it = 0; it < 2; it++) {
            int idx = tid + it * 256;
            int row = idx >> 2;
            int c4  = idx & 3;
            size_t goA = (size_t)(m0 + row) * D_MODEL + k0 + c4 * 4;
            size_t goB = (size_t)(n0g + row) * D_MODEL + k0 + c4 * 4;
            uint32_t so = (uint32_t)(row * G_STR + c4 * 4) * 4;
            cp_async16(base + so, Ah + goA);
            cp_async16(base + STG_AL * 4 + so, Al + goA);
            cp_async16(base + STG_B * 4 + so, Bt + goB);
        }
        cp_commit();
    };

    const int NT = D_MODEL / GBK;
    issue(0);
    issue(1);

    for (int t = 0; t < NT; t++) {
        if (t + 1 < NT) cp_wait<1>(); else cp_wait<0>();
        __syncthreads();

        const float* As  = sm + (t % 3) * STG_SZ;
        const float* Als = As + STG_AL;
        const float* Bs  = As + STG_B;

#pragma unroll
        for (int kk = 0; kk < GBK; kk += 8) {
            uint32_t ah[2][4], al[2][4];
#pragma unroll
            for (int i = 0; i < 2; i++) {
                int r = (wm * 32 + i * 16 + g) * G_STR + kk + t4;
                ah[i][0] = fau(As[r]);
                ah[i][1] = fau(As[r + 8 * G_STR]);
                ah[i][2] = fau(As[r + 4]);
                ah[i][3] = fau(As[r + 8 * G_STR + 4]);
                al[i][0] = fau(Als[r]);
                al[i][1] = fau(Als[r + 8 * G_STR]);
                al[i][2] = fau(Als[r + 4]);
                al[i][3] = fau(Als[r + 8 * G_STR + 4]);
            }
#pragma unroll
            for (int j = 0; j < 8; j++) {
                int rb = (wn * 64 + j * 8 + g) * G_STR + kk + t4;
                uint32_t bh0 = fau(Bs[rb]);
                uint32_t bh1 = fau(Bs[rb + 4]);
#pragma unroll
                for (int i = 0; i < 2; i++) {
                    mma_tf32(acc[i][j], ah[i], bh0, bh1);
                    mma_tf32(acc[i][j], al[i], bh0, bh1);
                }
            }
        }

        if (t + 2 < NT) issue(t + 2);
    }

    // epilogue: runtime segment routing
    const int rope  = (seg < 2);
    const int tfout = (seg > 0);
    float* dst = (seg == 0) ? Qo : (seg == 1) ? Ko : Vo;

    float invf[8];
    if (rope) {
#pragma unroll
        for (int j = 0; j < 8; j++) {
            int p = ((wn * 64 + j * 8 + 2 * t4) & 63) >> 1;
            invf[j] = powf(10000.0f, -(float)(2 * p) / (float)D_K);
        }
    }
#pragma unroll
    for (int i = 0; i < 2; i++) {
        int r1 = m0 + wm * 32 + i * 16 + g;
        int r2 = r1 + 8;
        float p1 = 0.f, p2 = 0.f;
        if (rope) { p1 = (float)pos[r1]; p2 = (float)pos[r2]; }
#pragma unroll
        for (int j = 0; j < 8; j++) {
            int c = n0 + wn * 64 + j * 8 + 2 * t4;
            float v0 = acc[i][j][0], v1 = acc[i][j][1];
            float v2 = acc[i][j][2], v3 = acc[i][j][3];
            if (rope) {
                float s, cs;
                sincosf(p1 * invf[j], &s, &cs);
                float u0 = v0 * cs - v1 * s, u1 = v0 * s + v1 * cs;
                v0 = u0; v1 = u1;
                sincosf(p2 * invf[j], &s, &cs);
                float u2 = v2 * cs - v3 * s, u3 = v2 * s + v3 * cs;
                v2 = u2; v3 = u3;
            }
            if (tfout) {
                v0 = tf32r(v0); v1 = tf32r(v1); v2 = tf32r(v2); v3 = tf32r(v3);
            }
            *reinterpret_cast<float2*>(&dst[(size_t)r1 * D_MODEL + c]) = make_float2(v0, v1);
            *reinterpret_cast<float2*>(&dst[(size_t)r2 * D_MODEL + c]) = make_float2(v2, v3);
        }
    }
}

// Plain O-projection GEMM (R12-proven, no rope / no tfout)
__global__ __launch_bounds__(256, 2)
void gemm_o(const float* __restrict__ Ah, const float* __restrict__ Al,
            const float* __restrict__ Bt, float* __restrict__ C) {
    extern __shared__ float sm[];
    const uint32_t smem_base = (uint32_t)__cvta_generic_to_shared(sm);

    const int tid = threadIdx.x;
    const int m0 = blockIdx.y * GBM;
    const int n0 = blockIdx.x * GBN;
    const int w = tid >> 5, lane = tid & 31;
    const int g = lane >> 2, t4 = lane & 3;
    const int wm = w >> 1, wn = w & 1;

    float acc[2][8][4];
#pragma unroll
    for (int i = 0; i < 2; i++)
#pragma unroll
        for (int j = 0; j < 8; j++)
#pragma unroll
            for (int e = 0; e < 4; e++) acc[i][j][e] = 0.f;

    auto issue = [&](int t) {
        int k0 = t * GBK;
        uint32_t base = smem_base + (uint32_t)((t % 3) * STG_SZ) * 4;
#pragma unroll
        for (int it = 0; it < 2; it++) {
            int idx = tid + it * 256;
            int row = idx >> 2;
            int c4  = idx & 3;
            size_t goA = (size_t)(m0 + row) * D_MODEL + k0 + c4 * 4;
            size_t goB = (size_t)(n0 + row) * D_MODEL + k0 + c4 * 4;
            uint32_t so = (uint32_t)(row * G_STR + c4 * 4) * 4;
            cp_async16(base + so, Ah + goA);
            cp_async16(base + STG_AL * 4 + so, Al + goA);
            cp_async16(base + STG_B * 4 + so, Bt + goB);
        }
        cp_commit();
    };

    const int NT = D_MODEL / GBK;
    issue(0);
    issue(1);

    for (int t = 0; t < NT; t++) {
        if (t + 1 < NT) cp_wait<1>(); else cp_wait<0>();
        __syncthreads();

        const float* As  = sm + (t % 3) * STG_SZ;
        const float* Als = As + STG_AL;
        const float* Bs  = As + STG_B;

#pragma unroll
        for (int kk = 0; kk < GBK; kk += 8) {
            uint32_t ah[2][4], al[2][4];
#pragma unroll
            for (int i = 0; i < 2; i++) {
                int r = (wm * 32 + i * 16 + g) * G_STR + kk + t4;
                ah[i][0] = fau(As[r]);
                ah[i][1] = fau(As[r + 8 * G_STR]);
                ah[i][2] = fau(As[r + 4]);
                ah[i][3] = fau(As[r + 8 * G_STR + 4]);
                al[i][0] = fau(Als[r]);
                al[i][1] = fau(Als[r + 8 * G_STR]);
                al[i][2] = fau(Als[r + 4]);
                al[i][3] = fau(Als[r + 8 * G_STR + 4]);
            }
#pragma unroll
            for (int j = 0; j < 8; j++) {
                int rb = (wn * 64 + j * 8 + g) * G_STR + kk + t4;
                uint32_t bh0 = fau(Bs[rb]);
                uint32_t bh1 = fau(Bs[rb + 4]);
#pragma unroll
                for (int i = 0; i < 2; i++) {
                    mma_tf32(acc[i][j], ah[i], bh0, bh1);
                    mma_tf32(acc[i][j], al[i], bh0, bh1);
                }
            }
        }

        if (t + 2 < NT) issue(t + 2);
    }

#pragma unroll
    for (int i = 0; i < 2; i++) {
        int r1 = m0 + wm * 32 + i * 16 + g;
        int r2 = r1 + 8;
#pragma unroll
        for (int j = 0; j < 8; j++) {
            int c = n0 + wn * 64 + j * 8 + 2 * t4;
            *reinterpret_cast<float2*>(&C[(size_t)r1 * D_MODEL + c]) =
                make_float2(acc[i][j][0], acc[i][j][1]);
            *reinterpret_cast<float2*>(&C[(size_t)r2 * D_MODEL + c]) =
                make_float2(acc[i][j][2], acc[i][j][3]);
        }
    }
}

// ============ Flash attention (R12-proven), epilogue writes hi/lo planes ============
#define AQ 128
#define AK 64
#define KS_STR 68
#define V_STR  72
#define PS_STR 68
#define K_STAGE (AK * KS_STR)
#define V_STAGE (AK * V_STR)
#define ATTN_SMEM ((2 * K_STAGE + 2 * V_STAGE + AQ * PS_STR) * 4)

__global__ __launch_bounds__(256, 2)
void attn_mma_kernel(const float* __restrict__ Q, const float* __restrict__ K,
                     const float* __restrict__ V,
                     float* __restrict__ OH, float* __restrict__ OL) {
    extern __shared__ float sm[];
    float* Kb = sm;
    float* Vb = sm + 2 * K_STAGE;
    float* Ps = sm + 2 * K_STAGE + 2 * V_STAGE;

    const int h   = blockIdx.y;
    const int q0  = (gridDim.x - 1 - blockIdx.x) * AQ;
    const int tid = threadIdx.x;
    const int w = tid >> 5, lane = tid & 31;
    const int g = lane >> 2, t4 = lane & 3;
    const int wrow = q0 + w * 16;

    const uint32_t smem_base = (uint32_t)__cvta_generic_to_shared(sm);
    const int lr  = tid >> 4;
    const int lc4 = tid & 15;

    uint32_t qh[8][4];
    {
        const float* qb = Q + (size_t)wrow * D_MODEL + h * D_K;
#pragma unroll
        for (int kc = 0; kc < 8; kc++) {
            int c0 = kc * 8 + t4;
            qh[kc][0] = fau(tf32r(qb[(size_t)g * D_MODEL + c0] * 0.125f));
            qh[kc][1] = fau(tf32r(qb[(size_t)(g + 8) * D_MODEL + c0] * 0.125f));
            qh[kc][2] = fau(tf32r(qb[(size_t)g * D_MODEL + c0 + 4] * 0.125f));
            qh[kc][3] = fau(tf32r(qb[(size_t)(g + 8) * D_MODEL + c0 + 4] * 0.125f));
        }
    }

    float o[8][4];
#pragma unroll
    for (int j = 0; j < 8; j++)
#pragma unroll
        for (int e = 0; e < 4; e++) o[j][e] = 0.f;
    float m_a = -1e30f, m_b = -1e30f, l_a = 0.f, l_b = 0.f;

    const int nt = (q0 + AQ) / AK;

    auto issue_tile = [&](int t) {
        int kv0 = t * AK;
        int st  = t & 1;
        uint32_t kdst = smem_base + (st * K_STAGE) * 4;
        uint32_t vdst = smem_base + (2 * K_STAGE + st * V_STAGE) * 4;
#pragma unroll
        for (int it = 0; it < 4; it++) {
            int r  = lr + it * 16;
            const float* kg = &K[(size_t)(kv0 + r) * D_MODEL + h * D_K + lc4 * 4];
            const float* vg = &V[(size_t)(kv0 + r) * D_MODEL + h * D_K + lc4 * 4];
            cp_async16(kdst + (r * KS_STR + lc4 * 4) * 4, kg);
            cp_async16(vdst + (r * V_STR + lc4 * 4) * 4, vg);
        }
        cp_commit();
    };

    issue_tile(0);

    for (int t = 0; t < nt; t++) {
        if (t + 1 < nt) {
            issue_tile(t + 1);
            cp_wait<1>();
        } else {
            cp_wait<0>();
        }
        __syncthreads();

        const int kv0 = t * AK;
        const float* Ks = Kb + (t & 1) * K_STAGE;
        const float* Vs = Vb + (t & 1) * V_STAGE;

        if (kv0 <= wrow + 15) {
            float s[8][4];
#pragma unroll
            for (int j = 0; j < 8; j++)
#pragma unroll
                for (int e = 0; e < 4; e++) s[j][e] = 0.f;

#pragma unroll
            for (int kc = 0; kc < 8; kc++) {
#pragma unroll
                for (int j = 0; j < 8; j++) {
                    int rb = (j * 8 + g) * KS_STR + kc * 8 + t4;
                    uint32_t b0 = fau(Ks[rb]);
                    uint32_t b1 = fau(Ks[rb + 4]);
                    mma_tf32(s[j], qh[kc], b0, b1);
                }
            }

            if (kv0 + AK - 1 > wrow) {
#pragma unroll
                for (int j = 0; j < 8; j++) {
                    int col = kv0 + j * 8 + 2 * t4;
                    int ra = wrow + g, rb2 = wrow + g + 8;
                    if (col > ra)      s[j][0] = -1e30f;
                    if (col + 1 > ra)  s[j][1] = -1e30f;
                    if (col > rb2)     s[j][2] = -1e30f;
                    if (col + 1 > rb2) s[j][3] = -1e30f;
                }
            }

            float mx_a = -1e30f, mx_b = -1e30f;
#pragma unroll
            for (int j = 0; j < 8; j++) {
                mx_a = fmaxf(mx_a, fmaxf(s[j][0], s[j][1]));
                mx_b = fmaxf(mx_b, fmaxf(s[j][2], s[j][3]));
            }
            mx_a = fmaxf(mx_a, __shfl_xor_sync(0xffffffffu, mx_a, 1));
            mx_a = fmaxf(mx_a, __shfl_xor_sync(0xffffffffu, mx_a, 2));
            mx_b = fmaxf(mx_b, __shfl_xor_sync(0xffffffffu, mx_b, 1));
            mx_b = fmaxf(mx_b, __shfl_xor_sync(0xffffffffu, mx_b, 2));
            float nm_a = fmaxf(m_a, mx_a), nm_b = fmaxf(m_b, mx_b);
            float al_a = __expf(m_a - nm_a), al_b = __expf(m_b - nm_b);
            m_a = nm_a; m_b = nm_b;

            float sum_a = 0.f, sum_b = 0.f;
#pragma unroll
            for (int j = 0; j < 8; j++) {
                float p0 = __expf(s[j][0] - m_a);
                float p1 = __expf(s[j][1] - m_a);
                float p2 = __expf(s[j][2] - m_b);
                float p3 = __expf(s[j][3] - m_b);
                sum_a += p0 + p1;
                sum_b += p2 + p3;
                o[j][0] *= al_a; o[j][1] *= al_a;
                o[j][2] *= al_b; o[j][3] *= al_b;
                float2 pa = make_float2(tf32r(p0), tf32r(p1));
                float2 pb = make_float2(tf32r(p2), tf32r(p3));
                *reinterpret_cast<float2*>(&Ps[(w * 16 + g) * PS_STR + j * 8 + 2 * t4]) = pa;
                *reinterpret_cast<float2*>(&Ps[(w * 16 + g + 8) * PS_STR + j * 8 + 2 * t4]) = pb;
            }
            sum_a += __shfl_xor_sync(0xffffffffu, sum_a, 1);
            sum_a += __shfl_xor_sync(0xffffffffu, sum_a, 2);
            sum_b += __shfl_xor_sync(0xffffffffu, sum_b, 1);
            sum_b += __shfl_xor_sync(0xffffffffu, sum_b, 2);
            l_a = l_a * al_a + sum_a;
            l_b = l_b * al_b + sum_b;
            __syncwarp();

#pragma unroll
            for (int kc = 0; kc < 8; kc++) {
                uint32_t pa[4];
                int pr = (w * 16 + g) * PS_STR + kc * 8 + t4;
                pa[0] = fau(Ps[pr]);
                pa[1] = fau(Ps[pr + 8 * PS_STR]);
                pa[2] = fau(Ps[pr + 4]);
                pa[3] = fau(Ps[pr + 8 * PS_STR + 4]);
#pragma unroll
                for (int j = 0; j < 8; j++) {
                    int vb = (kc * 8 + t4) * V_STR + j * 8 + g;
                    uint32_t b0 = fau(Vs[vb]);
                    uint32_t b1 = fau(Vs[vb + 4 * V_STR]);
                    mma_tf32(o[j], pa, b0, b1);
                }
            }
        }
        __syncthreads();
    }

    // epilogue: write hi/lo planes directly (bit-identical to Ap + split_kernel)
    float ia = 1.0f / l_a, ib = 1.0f / l_b;
#pragma unroll
    for (int j = 0; j < 8; j++) {
        int c = h * D_K + j * 8 + 2 * t4;
        float v0 = o[j][0] * ia, v1 = o[j][1] * ia;
        float v2 = o[j][2] * ib, v3 = o[j][3] * ib;
        float h0 = tf32r(v0), h1 = tf32r(v1), h2 = tf32r(v2), h3 = tf32r(v3);
        size_t b1 = (size_t)(wrow + g) * D_MODEL + c;
        size_t b2 = (size_t)(wrow + g + 8) * D_MODEL + c;
        *reinterpret_cast<float2*>(&OH[b1]) = make_float2(h0, h1);
        *reinterpret_cast<float2*>(&OH[b2]) = make_float2(h2, h3);
        *reinterpret_cast<float2*>(&OL[b1]) = make_float2(tf32r(v0 - h0), tf32r(v1 - h1));
        *reinterpret_cast<float2*>(&OL[b2]) = make_float2(tf32r(v2 - h2), tf32r(v3 - h3));
    }
}

// ---------------- launcher ----------------
extern "C" void kernel_launch(void* const* d_in, const int* in_sizes, int n_in,
                              void* d_out, int out_size) {
    const float* x  = (const float*)d_in[0];
    const float* Wq = (const float*)d_in[1];
    const float* Wk = (const float*)d_in[2];
    const float* Wv = (const float*)d_in[3];
    const float* Wo = (const float*)d_in[4];
    const int*  pos = (const int*)d_in[5];
    float* out = (float*)d_out;

    float *Qp, *Kp, *Vp, *XH, *XL, *W123;
    cudaGetSymbolAddress((void**)&Qp, g_Q);
    cudaGetSymbolAddress((void**)&Kp, g_K);
    cudaGetSymbolAddress((void**)&Vp, g_V);
    cudaGetSymbolAddress((void**)&XH, g_XH);
    cudaGetSymbolAddress((void**)&XL, g_XL);
    cudaGetSymbolAddress((void**)&W123, g_W123);

    cudaFuncSetAttribute(gemm_qkv, cudaFuncAttributeMaxDynamicSharedMemorySize, GEMM_SMEM);
    cudaFuncSetAttribute(gemm_o, cudaFuncAttributeMaxDynamicSharedMemorySize, GEMM_SMEM);
    cudaFuncSetAttribute(attn_mma_kernel, cudaFuncAttributeMaxDynamicSharedMemorySize, ATTN_SMEM);

    const int NX4 = S_LEN * D_MODEL / 4;
    const int NW4 = D_MODEL * D_MODEL / 4;
    dim3 qkvgrid(3 * D_MODEL / GBN, S_LEN / GBM);  // (24, 32)
    dim3 ogrid(D_MODEL / GBN, S_LEN / GBM);        // (8, 32)
    dim3 agrid(S_LEN / AQ, NUM_HEADS);             // (32, 16)

    // prepasses
    split_kernel<<<(NX4 + 255) / 256, 256>>>((const float4*)x, (float4*)XH, (float4*)XL, NX4);
    round3_kernel<<<(NW4 + 255) / 256, 256>>>((const float4*)Wq, (const float4*)Wk,
                                              (const float4*)Wv, (float4*)W123, NW4);

    // merged Q/K/V projections
    gemm_qkv<<<qkvgrid, 256, GEMM_SMEM>>>(XH, XL, W123, Qp, Kp, Vp, pos);

    // attention (writes hi/lo planes for the O projection)
    attn_mma_kernel<<<agrid, 256, ATTN_SMEM>>>(Qp, Kp, Vp, XH, XL);

    // O projection
    round1_kernel<<<(NW4 + 255) / 256, 256>>>((const float4*)Wo, (float4*)W123, NW4);
    gemm_o<<<ogrid, 256, GEMM_SMEM>>>(XH, XL, W123, out);
}

// round 17
// speedup vs baseline: 1.3957x; 1.1056x over previous
#include <cuda_runtime.h>
#include <math.h>
#include <stdint.h>

#define S_LEN 4096
#define D_MODEL 1024
#define NUM_HEADS 16
#define D_K 64

// ---------------- scratch (no allocs allowed) ----------------
__device__ float g_Q[S_LEN * D_MODEL];
__device__ float g_K[S_LEN * D_MODEL];
__device__ float g_V[S_LEN * D_MODEL];
__device__ float g_XH[S_LEN * D_MODEL];      // hi plane of activations
__device__ float g_XL[S_LEN * D_MODEL];      // lo plane of activations
__device__ float g_W123[3 * D_MODEL * D_MODEL]; // tf32 Wq|Wk|Wv merged (then Wo reuses)

// ---------------- helpers ----------------
__device__ __forceinline__ float tf32r(float x) {
    uint32_t u;
    asm("cvt.rna.tf32.f32 %0, %1;" : "=r"(u) : "f"(x));
    return __uint_as_float(u);
}
__device__ __forceinline__ uint32_t fau(float x) { return __float_as_uint(x); }

__device__ __forceinline__ void mma_tf32(float* d, const uint32_t* a, uint32_t b0, uint32_t b1) {
    asm volatile(
        "mma.sync.aligned.m16n8k8.row.col.f32.tf32.tf32.f32 "
        "{%0,%1,%2,%3}, {%4,%5,%6,%7}, {%8,%9}, {%0,%1,%2,%3};"
        : "+f"(d[0]), "+f"(d[1]), "+f"(d[2]), "+f"(d[3])
        : "r"(a[0]), "r"(a[1]), "r"(a[2]), "r"(a[3]), "r"(b0), "r"(b1));
}

// ldmatrix on 32-bit data (each lane receives one fp32 as 2x b16 halves)
__device__ __forceinline__ void ldsm_x4(uint32_t& r0, uint32_t& r1, uint32_t& r2,
                                        uint32_t& r3, uint32_t a) {
    asm volatile("ldmatrix.sync.aligned.m8n8.x4.shared.b16 {%0,%1,%2,%3}, [%4];"
                 : "=r"(r0), "=r"(r1), "=r"(r2), "=r"(r3) : "r"(a));
}

__device__ __forceinline__ void cp_async16(uint32_t smem_addr, const void* gptr) {
    asm volatile("cp.async.cg.shared.global [%0], [%1], 16;\n"
                 :: "r"(smem_addr), "l"(gptr));
}
__device__ __forceinline__ void cp_commit() {
    asm volatile("cp.async.commit_group;\n" ::: "memory");
}
template<int N>
__device__ __forceinline__ void cp_wait() {
    asm volatile("cp.async.wait_group %0;\n" :: "n"(N) : "memory");
}

// ---------------- prepasses ----------------
__global__ void split_kernel(const float4* __restrict__ src, float4* __restrict__ hi,
                             float4* __restrict__ lo, int n4) {
    int i = blockIdx.x * blockDim.x + threadIdx.x;
    if (i >= n4) return;
    float4 v = src[i];
    float4 h, l;
    h.x = tf32r(v.x); l.x = tf32r(v.x - h.x);
    h.y = tf32r(v.y); l.y = tf32r(v.y - h.y);
    h.z = tf32r(v.z); l.z = tf32r(v.z - h.z);
    h.w = tf32r(v.w); l.w = tf32r(v.w - h.w);
    hi[i] = h; lo[i] = l;
}

__global__ void round3_kernel(const float4* __restrict__ s1, const float4* __restrict__ s2,
                              const float4* __restrict__ s3, float4* __restrict__ dst, int n4) {
    int i = blockIdx.x * blockDim.x + threadIdx.x;
    if (i >= n4) return;
    float4 v = s1[i];
    float4 h;
    h.x = tf32r(v.x); h.y = tf32r(v.y); h.z = tf32r(v.z); h.w = tf32r(v.w);
    dst[i] = h;
    v = s2[i];
    h.x = tf32r(v.x); h.y = tf32r(v.y); h.z = tf32r(v.z); h.w = tf32r(v.w);
    dst[i + n4] = h;
    v = s3[i];
    h.x = tf32r(v.x); h.y = tf32r(v.y); h.z = tf32r(v.z); h.w = tf32r(v.w);
    dst[i + 2 * n4] = h;
}

__global__ void round1_kernel(const float4* __restrict__ src, float4* __restrict__ dst, int n4) {
    int i = blockIdx.x * blockDim.x + threadIdx.x;
    if (i >= n4) return;
    float4 v = src[i];
    float4 h;
    h.x = tf32r(v.x); h.y = tf32r(v.y); h.z = tf32r(v.z); h.w = tf32r(v.w);
    dst[i] = h;
}

// ---------------- 2xTF32 pipelined GEMM core (R12 mainloop + ldmatrix loads) ----------------
#define GBM 128
#define GBN 128
#define GBK 16
#define G_STR 20
#define STG_AL (128 * G_STR)
#define STG_B  (256 * G_STR)
#define STG_SZ (3 * 128 * G_STR)      // 7680 floats per stage
#define GEMM_SMEM (3 * STG_SZ * 4)    // 92160 B

// Merged QKV GEMM: B is [3*D_MODEL, D_MODEL]; segment routing in epilogue.
__global__ __launch_bounds__(256, 2)
void gemm_qkv(const float* __restrict__ Ah, const float* __restrict__ Al,
              const float* __restrict__ Bt, float* __restrict__ Qo,
              float* __restrict__ Ko, float* __restrict__ Vo,
              const int* __restrict__ pos) {
    extern __shared__ float sm[];
    const uint32_t smem_base = (uint32_t)__cvta_generic_to_shared(sm);

    const int tid = threadIdx.x;
    const int m0 = blockIdx.y * GBM;
    const int n0g = blockIdx.x * GBN;
    const int seg = blockIdx.x >> 3;
    const int n0 = n0g & (D_MODEL - 1);
    const int w = tid >> 5, lane = tid & 31;
    const int g = lane >> 2, t4 = lane & 3;
    const int wm = w >> 1, wn = w & 1;
    const int tix = lane >> 3, rr = lane & 7;   // ldmatrix tile idx / row

    // per-lane ldmatrix byte offsets
    const uint32_t laneA = (uint32_t)(((wm * 32 + (tix & 1) * 8 + rr) * G_STR + (tix >> 1) * 4) * 4);
    const uint32_t laneB = (uint32_t)(((wn * 64 + (tix >> 1) * 8 + rr) * G_STR + (tix & 1) * 4) * 4);

    float acc[2][8][4];
#pragma unroll
    for (int i = 0; i < 2; i++)
#pragma unroll
        for (int j = 0; j < 8; j++)
#pragma unroll
            for (int e = 0; e < 4; e++) acc[i][j][e] = 0.f;

    auto issue = [&](int t) {
        int k0 = t * GBK;
        uint32_t base = smem_base + (uint32_t)((t % 3) * STG_SZ) * 4;
#pragma unroll
        for (int it = 0; it < 2; it++) {
            int idx = tid + it * 256;
            int row = idx >> 2;
            int c4  = idx & 3;
            size_t goA = (size_t)(m0 + row) * D_MODEL + k0 + c4 * 4;
            size_t goB = (size_t)(n0g + row) * D_MODEL + k0 + c4 * 4;
            uint32_t so = (uint32_t)(row * G_STR + c4 * 4) * 4;
            cp_async16(base + so, Ah + goA);
            cp_async16(base + STG_AL * 4 + so, Al + goA);
            cp_async16(base + STG_B * 4 + so, Bt + goB);
        }
        cp_commit();
    };

    const int NT = D_MODEL / GBK;
    issue(0);
    issue(1);

    for (int t = 0; t < NT; t++) {
        if (t + 1 < NT) cp_wait<1>(); else cp_wait<0>();
        __syncthreads();

        const uint32_t as_a  = smem_base + (uint32_t)((t % 3) * STG_SZ) * 4;
        const uint32_t as_al = as_a + STG_AL * 4;
        const uint32_t as_b  = as_a + STG_B * 4;

#pragma unroll
        for (int kk = 0; kk < GBK; kk += 8) {
            uint32_t ah[2][4], al[2][4];
#pragma unroll
            for (int i = 0; i < 2; i++) {
                uint32_t off = laneA + (uint32_t)((i * 16 * G_STR + kk) * 4);
                ldsm_x4(ah[i][0], ah[i][1], ah[i][2], ah[i][3], as_a + off);
                ldsm_x4(al[i][0], al[i][1], al[i][2], al[i][3], as_al + off);
            }
#pragma unroll
            for (int jp = 0; jp < 4; jp++) {
                uint32_t b[4];
                ldsm_x4(b[0], b[1], b[2], b[3],
                        as_b + laneB + (uint32_t)((jp * 16 * G_STR + kk) * 4));
#pragma unroll
                for (int i = 0; i < 2; i++) {
                    mma_tf32(acc[i][2 * jp],     ah[i], b[0], b[1]);
                    mma_tf32(acc[i][2 * jp],     al[i], b[0], b[1]);
                    mma_tf32(acc[i][2 * jp + 1], ah[i], b[2], b[3]);
                    mma_tf32(acc[i][2 * jp + 1], al[i], b[2], b[3]);
                }
            }
        }

        if (t + 2 < NT) issue(t + 2);
    }

    // epilogue: runtime segment routing
    const int rope  = (seg < 2);
    const int tfout = (seg > 0);
    float* dst = (seg == 0) ? Qo : (seg == 1) ? Ko : Vo;

    float invf[8];
    if (rope) {
#pragma unroll
        for (int j = 0; j < 8; j++) {
            int p = ((wn * 64 + j * 8 + 2 * t4) & 63) >> 1;
            invf[j] = powf(10000.0f, -(float)(2 * p) / (float)D_K);
        }
    }
#pragma unroll
    for (int i = 0; i < 2; i++) {
        int r1 = m0 + wm * 32 + i * 16 + g;
        int r2 = r1 + 8;
        float p1 = 0.f, p2 = 0.f;
        if (rope) { p1 = (float)pos[r1]; p2 = (float)pos[r2]; }
#pragma unroll
        for (int j = 0; j < 8; j++) {
            int c = n0 + wn * 64 + j * 8 + 2 * t4;
            float v0 = acc[i][j][0], v1 = acc[i][j][1];
            float v2 = acc[i][j][2], v3 = acc[i][j][3];
            if (rope) {
                float s, cs;
                sincosf(p1 * invf[j], &s, &cs);
                float u0 = v0 * cs - v1 * s, u1 = v0 * s + v1 * cs;
                v0 = u0; v1 = u1;
                sincosf(p2 * invf[j], &s, &cs);
                float u2 = v2 * cs - v3 * s, u3 = v2 * s + v3 * cs;
                v2 = u2; v3 = u3;
            }
            if (tfout) {
                v0 = tf32r(v0); v1 = tf32r(v1); v2 = tf32r(v2); v3 = tf32r(v3);
            }
            *reinterpret_cast<float2*>(&dst[(size_t)r1 * D_MODEL + c]) = make_float2(v0, v1);
            *reinterpret_cast<float2*>(&dst[(size_t)r2 * D_MODEL + c]) = make_float2(v2, v3);
        }
    }
}

// Plain O-projection GEMM (same mainloop, no rope / no tfout)
__global__ __launch_bounds__(256, 2)
void gemm_o(const float* __restrict__ Ah, const float* __restrict__ Al,
            const float* __restrict__ Bt, float* __restrict__ C) {
    extern __shared__ float sm[];
    const uint32_t smem_base = (uint32_t)__cvta_generic_to_shared(sm);

    const int tid = threadIdx.x;
    const int m0 = blockIdx.y * GBM;
    const int n0 = blockIdx.x * GBN;
    const int w = tid >> 5, lane = tid & 31;
    const int g = lane >> 2, t4 = lane & 3;
    const int wm = w >> 1, wn = w & 1;
    const int tix = lane >> 3, rr = lane & 7;

    const uint32_t laneA = (uint32_t)(((wm * 32 + (tix & 1) * 8 + rr) * G_STR + (tix >> 1) * 4) * 4);
    const uint32_t laneB = (uint32_t)(((wn * 64 + (tix >> 1) * 8 + rr) * G_STR + (tix & 1) * 4) * 4);

    float acc[2][8][4];
#pragma unroll
    for (int i = 0; i < 2; i++)
#pragma unroll
        for (int j = 0; j < 8; j++)
#pragma unroll
            for (int e = 0; e < 4; e++) acc[i][j][e] = 0.f;

    auto issue = [&](int t) {
        int k0 = t * GBK;
        uint32_t base = smem_base + (uint32_t)((t % 3) * STG_SZ) * 4;
#pragma unroll
        for (int it = 0; it < 2; it++) {
            int idx = tid + it * 256;
            int row = idx >> 2;
            int c4  = idx & 3;
            size_t goA = (size_t)(m0 + row) * D_MODEL + k0 + c4 * 4;
            size_t goB = (size_t)(n0 + row) * D_MODEL + k0 + c4 * 4;
            uint32_t so = (uint32_t)(row * G_STR + c4 * 4) * 4;
            cp_async16(base + so, Ah + goA);
            cp_async16(base + STG_AL * 4 + so, Al + goA);
            cp_async16(base + STG_B * 4 + so, Bt + goB);
        }
        cp_commit();
    };

    const int NT = D_MODEL / GBK;
    issue(0);
    issue(1);

    for (int t = 0; t < NT; t++) {
        if (t + 1 < NT) cp_wait<1>(); else cp_wait<0>();
        __syncthreads();

        const uint32_t as_a  = smem_base + (uint32_t)((t % 3) * STG_SZ) * 4;
        const uint32_t as_al = as_a + STG_AL * 4;
        const uint32_t as_b  = as_a + STG_B * 4;

#pragma unroll
        for (int kk = 0; kk < GBK; kk += 8) {
            uint32_t ah[2][4], al[2][4];
#pragma unroll
            for (int i = 0; i < 2; i++) {
                uint32_t off = laneA + (uint32_t)((i * 16 * G_STR + kk) * 4);
                ldsm_x4(ah[i][0], ah[i][1], ah[i][2], ah[i][3], as_a + off);
                ldsm_x4(al[i][0], al[i][1], al[i][2], al[i][3], as_al + off);
            }
#pragma unroll
            for (int jp = 0; jp < 4; jp++) {
                uint32_t b[4];
                ldsm_x4(b[0], b[1], b[2], b[3],
                        as_b + laneB + (uint32_t)((jp * 16 * G_STR + kk) * 4));
#pragma unroll
                for (int i = 0; i < 2; i++) {
                    mma_tf32(acc[i][2 * jp],     ah[i], b[0], b[1]);
                    mma_tf32(acc[i][2 * jp],     al[i], b[0], b[1]);
                    mma_tf32(acc[i][2 * jp + 1], ah[i], b[2], b[3]);
                    mma_tf32(acc[i][2 * jp + 1], al[i], b[2], b[3]);
                }
            }
        }

        if (t + 2 < NT) issue(t + 2);
    }

#pragma unroll
    for (int i = 0; i < 2; i++) {
        int r1 = m0 + wm * 32 + i * 16 + g;
        int r2 = r1 + 8;
#pragma unroll
        for (int j = 0; j < 8; j++) {
            int c = n0 + wn * 64 + j * 8 + 2 * t4;
            *reinterpret_cast<float2*>(&C[(size_t)r1 * D_MODEL + c]) =
                make_float2(acc[i][j][0], acc[i][j][1]);
            *reinterpret_cast<float2*>(&C[(size_t)r2 * D_MODEL + c]) =
                make_float2(acc[i][j][2], acc[i][j][3]);
        }
    }
}

// ============ Flash attention (R16 structure + ldmatrix K/P loads) ============
#define AQ 128
#define AK 64
#define KS_STR 68
#define V_STR  72
#define PS_STR 68
#define K_STAGE (AK * KS_STR)
#define V_STAGE (AK * V_STR)
#define ATTN_SMEM ((2 * K_STAGE + 2 * V_STAGE + AQ * PS_STR) * 4)

__global__ __launch_bounds__(256, 2)
void attn_mma_kernel(const float* __restrict__ Q, const float* __restrict__ K,
                     const float* __restrict__ V,
                     float* __restrict__ OH, float* __restrict__ OL) {
    extern __shared__ float sm[];
    float* Kb = sm;
    float* Vb = sm + 2 * K_STAGE;
    float* Ps = sm + 2 * K_STAGE + 2 * V_STAGE;

    const int h   = blockIdx.y;
    const int q0  = (gridDim.x - 1 - blockIdx.x) * AQ;
    const int tid = threadIdx.x;
    const int w = tid >> 5, lane = tid & 31;
    const int g = lane >> 2, t4 = lane & 3;
    const int wrow = q0 + w * 16;
    const int tix = lane >> 3, rr = lane & 7;

    const uint32_t smem_base = (uint32_t)__cvta_generic_to_shared(sm);
    const int lr  = tid >> 4;
    const int lc4 = tid & 15;

    // per-lane ldmatrix offsets (bytes)
    const uint32_t laneK = (uint32_t)((((tix >> 1) * 8 + rr) * KS_STR + (tix & 1) * 4) * 4);
    const uint32_t laneP = (uint32_t)(((w * 16 + (tix & 1) * 8 + rr) * PS_STR + (tix >> 1) * 4) * 4);
    const uint32_t ps_addr = smem_base + (uint32_t)((2 * K_STAGE + 2 * V_STAGE) * 4);

    uint32_t qh[8][4];
    {
        const float* qb = Q + (size_t)wrow * D_MODEL + h * D_K;
#pragma unroll
        for (int kc = 0; kc < 8; kc++) {
            int c0 = kc * 8 + t4;
            qh[kc][0] = fau(tf32r(qb[(size_t)g * D_MODEL + c0] * 0.125f));
            qh[kc][1] = fau(tf32r(qb[(size_t)(g + 8) * D_MODEL + c0] * 0.125f));
            qh[kc][2] = fau(tf32r(qb[(size_t)g * D_MODEL + c0 + 4] * 0.125f));
            qh[kc][3] = fau(tf32r(qb[(size_t)(g + 8) * D_MODEL + c0 + 4] * 0.125f));
        }
    }

    float o[8][4];
#pragma unroll
    for (int j = 0; j < 8; j++)
#pragma unroll
        for (int e = 0; e < 4; e++) o[j][e] = 0.f;
    float m_a = -1e30f, m_b = -1e30f, l_a = 0.f, l_b = 0.f;

    const int nt = (q0 + AQ) / AK;

    auto issue_tile = [&](int t) {
        int kv0 = t * AK;
        int st  = t & 1;
        uint32_t kdst = smem_base + (st * K_STAGE) * 4;
        uint32_t vdst = smem_base + (2 * K_STAGE + st * V_STAGE) * 4;
#pragma unroll
        for (int it = 0; it < 4; it++) {
            int r  = lr + it * 16;
            const float* kg = &K[(size_t)(kv0 + r) * D_MODEL + h * D_K + lc4 * 4];
            const float* vg = &V[(size_t)(kv0 + r) * D_MODEL + h * D_K + lc4 * 4];
            cp_async16(kdst + (r * KS_STR + lc4 * 4) * 4, kg);
            cp_async16(vdst + (r * V_STR + lc4 * 4) * 4, vg);
        }
        cp_commit();
    };

    issue_tile(0);

    for (int t = 0; t < nt; t++) {
        if (t + 1 < nt) {
            issue_tile(t + 1);
            cp_wait<1>();
        } else {
            cp_wait<0>();
        }
        __syncthreads();

        const int kv0 = t * AK;
        const uint32_t kst = smem_base + (uint32_t)(((t & 1) * K_STAGE) * 4);
        const float* Vs = Vb + (t & 1) * V_STAGE;

        if (kv0 <= wrow + 15) {
            float s[8][4];
#pragma unroll
            for (int j = 0; j < 8; j++)
#pragma unroll
                for (int e = 0; e < 4; e++) s[j][e] = 0.f;

#pragma unroll
            for (int kc = 0; kc < 8; kc++) {
#pragma unroll
                for (int jp = 0; jp < 4; jp++) {
                    uint32_t b[4];
                    ldsm_x4(b[0], b[1], b[2], b[3],
                            kst + laneK + (uint32_t)((jp * 16 * KS_STR + kc * 8) * 4));
                    mma_tf32(s[2 * jp],     qh[kc], b[0], b[1]);
                    mma_tf32(s[2 * jp + 1], qh[kc], b[2], b[3]);
                }
            }

            if (kv0 + AK - 1 > wrow) {
#pragma unroll
                for (int j = 0; j < 8; j++) {
                    int col = kv0 + j * 8 + 2 * t4;
                    int ra = wrow + g, rb2 = wrow + g + 8;
                    if (col > ra)      s[j][0] = -1e30f;
                    if (col + 1 > ra)  s[j][1] = -1e30f;
                    if (col > rb2)     s[j][2] = -1e30f;
                    if (col + 1 > rb2) s[j][3] = -1e30f;
                }
            }

            float mx_a = -1e30f, mx_b = -1e30f;
#pragma unroll
            for (int j = 0; j < 8; j++) {
                mx_a = fmaxf(mx_a, fmaxf(s[j][0], s[j][1]));
                mx_b = fmaxf(mx_b, fmaxf(s[j][2], s[j][3]));
            }
            mx_a = fmaxf(mx_a, __shfl_xor_sync(0xffffffffu, mx_a, 1));
            mx_a = fmaxf(mx_a, __shfl_xor_sync(0xffffffffu, mx_a, 2));
            mx_b = fmaxf(mx_b, __shfl_xor_sync(0xffffffffu, mx_b, 1));
            mx_b = fmaxf(mx_b, __shfl_xor_sync(0xffffffffu, mx_b, 2));
            float nm_a = fmaxf(m_a, mx_a), nm_b = fmaxf(m_b, mx_b);
            float al_a = __expf(m_a - nm_a), al_b = __expf(m_b - nm_b);
            m_a = nm_a; m_b = nm_b;

            float sum_a = 0.f, sum_b = 0.f;
#pragma unroll
            for (int j = 0; j < 8; j++) {
                float p0 = __expf(s[j][0] - m_a);
                float p1 = __expf(s[j][1] - m_a);
                float p2 = __expf(s[j][2] - m_b);
                float p3 = __expf(s[j][3] - m_b);
                sum_a += p0 + p1;
                sum_b += p2 + p3;
                o[j][0] *= al_a; o[j][1] *= al_a;
                o[j][2] *= al_b; o[j][3] *= al_b;
                float2 pa = make_float2(tf32r(p0), tf32r(p1));
                float2 pb = make_float2(tf32r(p2), tf32r(p3));
                *reinterpret_cast<float2*>(&Ps[(w * 16 + g) * PS_STR + j * 8 + 2 * t4]) = pa;
                *reinterpret_cast<float2*>(&Ps[(w * 16 + g + 8) * PS_STR + j * 8 + 2 * t4]) = pb;
            }
            sum_a += __shfl_xor_sync(0xffffffffu, sum_a, 1);
            sum_a += __shfl_xor_sync(0xffffffffu, sum_a, 2);
            sum_b += __shfl_xor_sync(0xffffffffu, sum_b, 1);
            sum_b += __shfl_xor_sync(0xffffffffu, sum_b, 2);
            l_a = l_a * al_a + sum_a;
            l_b = l_b * al_b + sum_b;
            __syncwarp();

#pragma unroll
            for (int kc = 0; kc < 8; kc++) {
                uint32_t pa[4];
                ldsm_x4(pa[0], pa[1], pa[2], pa[3],
                        ps_addr + laneP + (uint32_t)(kc * 32));
#pragma unroll
                for (int j = 0; j < 8; j++) {
                    int vb = (kc * 8 + t4) * V_STR + j * 8 + g;
                    uint32_t b0 = fau(Vs[vb]);
                    uint32_t b1 = fau(Vs[vb + 4 * V_STR]);
                    mma_tf32(o[j], pa, b0, b1);
                }
            }
        }
        __syncthreads();
    }

    // epilogue: write hi/lo planes directly
    float ia = 1.0f / l_a, ib = 1.0f / l_b;
#pragma unroll
    for (int j = 0; j < 8; j++) {
        int c = h * D_K + j * 8 + 2 * t4;
        float v0 = o[j][0] * ia, v1 = o[j][1] * ia;
        float v2 = o[j][2] * ib, v3 = o[j][3] * ib;
        float h0 = tf32r(v0), h1 = tf32r(v1), h2 = tf32r(v2), h3 = tf32r(v3);
        size_t b1 = (size_t)(wrow + g) * D_MODEL + c;
        size_t b2 = (size_t)(wrow + g + 8) * D_MODEL + c;
        *reinterpret_cast<float2*>(&OH[b1]) = make_float2(h0, h1);
        *reinterpret_cast<float2*>(&OH[b2]) = make_float2(h2, h3);
        *reinterpret_cast<float2*>(&OL[b1]) = make_float2(tf32r(v0 - h0), tf32r(v1 - h1));
        *reinterpret_cast<float2*>(&OL[b2]) = make_float2(tf32r(v2 - h2), tf32r(v3 - h3));
    }
}

// ---------------- launcher ----------------
extern "C" void kernel_launch(void* const* d_in, const int* in_sizes, int n_in,
                              void* d_out, int out_size) {
    const float* x  = (const float*)d_in[0];
    const float* Wq = (const float*)d_in[1];
    const float* Wk = (const float*)d_in[2];
    const float* Wv = (const float*)d_in[3];
    const float* Wo = (const float*)d_in[4];
    const int*  pos = (const int*)d_in[5];
    float* out = (float*)d_out;

    float *Qp, *Kp, *Vp, *XH, *XL, *W123;
    cudaGetSymbolAddress((void**)&Qp, g_Q);
    cudaGetSymbolAddress((void**)&Kp, g_K);
    cudaGetSymbolAddress((void**)&Vp, g_V);
    cudaGetSymbolAddress((void**)&XH, g_XH);
    cudaGetSymbolAddress((void**)&XL, g_XL);
    cudaGetSymbolAddress((void**)&W123, g_W123);

    cudaFuncSetAttribute(gemm_qkv, cudaFuncAttributeMaxDynamicSharedMemorySize, GEMM_SMEM);
    cudaFuncSetAttribute(gemm_o, cudaFuncAttributeMaxDynamicSharedMemorySize, GEMM_SMEM);
    cudaFuncSetAttribute(attn_mma_kernel, cudaFuncAttributeMaxDynamicSharedMemorySize, ATTN_SMEM);

    const int NX4 = S_LEN * D_MODEL / 4;
    const int NW4 = D_MODEL * D_MODEL / 4;
    dim3 qkvgrid(3 * D_MODEL / GBN, S_LEN / GBM);  // (24, 32)
    dim3 ogrid(D_MODEL / GBN, S_LEN / GBM);        // (8, 32)
    dim3 agrid(S_LEN / AQ, NUM_HEADS);             // (32, 16)

    split_kernel<<<(NX4 + 255) / 256, 256>>>((const float4*)x, (float4*)XH, (float4*)XL, NX4);
    round3_kernel<<<(NW4 + 255) / 256, 256>>>((const float4*)Wq, (const float4*)Wk,
                                              (const float4*)Wv, (float4*)W123, NW4);

    gemm_qkv<<<qkvgrid, 256, GEMM_SMEM>>>(XH, XL, W123, Qp, Kp, Vp, pos);

    attn_mma_kernel<<<agrid, 256, ATTN_SMEM>>>(Qp, Kp, Vp, XH, XL);

    round1_kernel<<<(NW4 + 255) / 256, 256>>>((const float4*)Wo, (float4*)W123, NW4);
    gemm_o<<<ogrid, 256, GEMM_SMEM>>>(XH, XL, W123, out);
}